// round 10
// baseline (speedup 1.0000x reference)
#include <cuda_runtime.h>
#include <cuda_bf16.h>
#include <cstdint>
#include <cstddef>

// ---------------------------------------------------------------------------
// Problem constants
// ---------------------------------------------------------------------------
#define B_SZ   4
#define NH_    4
#define HD_    32
#define C_DIM  128
#define WS_    8
#define L_WIN  64
#define NWIN   1024
#define N_IMG  65536
#define TD_    100
#define T_TOT  65736
#define M_TOT  (B_SZ * T_TOT)   // 262944
#define SCALE_ 0.17677669529663687f

// Scratch (device globals)
__device__ __nv_bfloat16 g_qkv_h[(size_t)M_TOT * 384];
__device__ __nv_bfloat16 g_qkv_l[(size_t)M_TOT * 384];
__device__ __nv_bfloat16 g_ctx_h[(size_t)M_TOT * 128];
__device__ __nv_bfloat16 g_ctx_l[(size_t)M_TOT * 128];
__device__ __nv_bfloat16 g_wq_h[384 * 128], g_wq_l[384 * 128];
__device__ __nv_bfloat16 g_wp_h[128 * 128], g_wp_l[128 * 128];
__device__ float g_bias[NH_ * L_WIN * L_WIN];

// ---------------------------------------------------------------------------
__device__ __forceinline__ const float* token_row(int r,
                                                  const float* __restrict__ x,
                                                  const float* __restrict__ det,
                                                  const float* __restrict__ inter)
{
    int b = r / T_TOT;
    int t = r - b * T_TOT;
    if (t < N_IMG)  return x     + ((size_t)b * N_IMG + t) * C_DIM;
    t -= N_IMG;
    if (t < TD_)    return det   + ((size_t)b * TD_   + t) * C_DIM;
    return inter + ((size_t)b * TD_ + (t - TD_)) * C_DIM;
}

__device__ __forceinline__ void mma_bf16(float c[4], const uint32_t a[4],
                                         uint32_t b0, uint32_t b1)
{
    asm volatile(
        "mma.sync.aligned.m16n8k16.row.col.f32.bf16.bf16.f32 "
        "{%0,%1,%2,%3}, {%4,%5,%6,%7}, {%8,%9}, {%0,%1,%2,%3};\n"
        : "+f"(c[0]), "+f"(c[1]), "+f"(c[2]), "+f"(c[3])
        : "r"(a[0]), "r"(a[1]), "r"(a[2]), "r"(a[3]), "r"(b0), "r"(b1));
}

__device__ __forceinline__ void ldm_x4(uint32_t r[4], const void* p)
{
    uint32_t sa = (uint32_t)__cvta_generic_to_shared(p);
    asm volatile("ldmatrix.sync.aligned.m8n8.x4.shared.b16 {%0,%1,%2,%3}, [%4];"
                 : "=r"(r[0]), "=r"(r[1]), "=r"(r[2]), "=r"(r[3]) : "r"(sa));
}

__device__ __forceinline__ void ldm_x4_t(uint32_t r[4], const void* p)
{
    uint32_t sa = (uint32_t)__cvta_generic_to_shared(p);
    asm volatile("ldmatrix.sync.aligned.m8n8.x4.trans.shared.b16 {%0,%1,%2,%3}, [%4];"
                 : "=r"(r[0]), "=r"(r[1]), "=r"(r[2]), "=r"(r[3]) : "r"(sa));
}

__device__ __forceinline__ uint32_t pack_bf16x2(float e0, float e1)
{
    uint32_t r;
    asm("cvt.rn.bf16x2.f32 %0, %1, %2;" : "=r"(r) : "f"(e1), "f"(e0));
    return r;
}

// split v0,v1 into hi/lo bf16 pairs and store as one uint32 each
__device__ __forceinline__ void split_store2(float v0, float v1,
                                             __nv_bfloat16* ph,
                                             __nv_bfloat16* pl, size_t off)
{
    float h0 = __bfloat162float(__float2bfloat16(v0));
    float h1 = __bfloat162float(__float2bfloat16(v1));
    *(uint32_t*)(ph + off) = pack_bf16x2(h0, h1);
    *(uint32_t*)(pl + off) = pack_bf16x2(v0 - h0, v1 - h1);
}

// reconstruct 8 fp32 from hi/lo uint4 pair
__device__ __forceinline__ void bf8_sum_to_f32(uint4 hv, uint4 lv, float* dst)
{
    const __nv_bfloat162* hp = (const __nv_bfloat162*)&hv;
    const __nv_bfloat162* lp = (const __nv_bfloat162*)&lv;
    #pragma unroll
    for (int i = 0; i < 4; i++) {
        float2 hf = __bfloat1622float2(hp[i]);
        float2 lf = __bfloat1622float2(lp[i]);
        dst[2 * i]     = hf.x + lf.x;
        dst[2 * i + 1] = hf.y + lf.y;
    }
}

// ---------------------------------------------------------------------------
// K0a: pregather rel-pos bias; K0b: split weights to bf16 hi/lo
// ---------------------------------------------------------------------------
__global__ void bias_gather_kernel(const float* __restrict__ rel_table,
                                   const int*   __restrict__ rel_index)
{
    int idx = blockIdx.x * 256 + threadIdx.x;
    if (idx < L_WIN * L_WIN) {
        int ri = rel_index[idx];
        #pragma unroll
        for (int h = 0; h < NH_; h++)
            g_bias[h * (L_WIN * L_WIN) + idx] = rel_table[ri * NH_ + h];
    }
}

__global__ void weight_split_kernel(const float* __restrict__ Wq,
                                    const float* __restrict__ Wp)
{
    int i = blockIdx.x * 256 + threadIdx.x;
    if (i < 384 * 128) {
        float v = Wq[i];
        __nv_bfloat16 h = __float2bfloat16(v);
        g_wq_h[i] = h;
        g_wq_l[i] = __float2bfloat16(v - __bfloat162float(h));
    }
    if (i < 128 * 128) {
        float v = Wp[i];
        __nv_bfloat16 h = __float2bfloat16(v);
        g_wp_h[i] = h;
        g_wp_l[i] = __float2bfloat16(v - __bfloat162float(h));
    }
}

// ---------------------------------------------------------------------------
// GEMM: A persisted in smem (full K=128, bf16 hi/lo), loop over n-blocks.
//   IS_QKV: A = tokens fp32 (converted once), NB=3, out = g_qkv hi/lo bf16
//   !IS_QKV: A = g_ctx bf16 (straight copies), NB=1, out = fp32 param
// Dynamic smem: Ah[128][136] Al[128][136] Bh[128][40] Bl[128][40] = 90112 B.
// ---------------------------------------------------------------------------
template<bool IS_QKV>
__global__ __launch_bounds__(256, 2)
void gemm_kernel(const float* __restrict__ x, const float* __restrict__ det,
                 const float* __restrict__ inter,
                 const float* __restrict__ bias, float* __restrict__ out_f32)
{
    extern __shared__ __align__(16) char smem_raw[];
    __nv_bfloat16* As_h = (__nv_bfloat16*)smem_raw;       // [128][136]
    __nv_bfloat16* As_l = As_h + 128 * 136;
    __nv_bfloat16* Bs_h = As_l + 128 * 136;               // [128][40]
    __nv_bfloat16* Bs_l = Bs_h + 128 * 40;

    const __nv_bfloat16* Wh = IS_QKV ? g_wq_h : g_wp_h;
    const __nv_bfloat16* Wl = IS_QKV ? g_wq_l : g_wp_l;

    const int m0 = blockIdx.x * 128;
    const int tid = threadIdx.x, lane = tid & 31, warp = tid >> 5;
    const int mbase = (warp >> 1) * 32;
    const int nbase = (warp & 1) * 64;

    // ---- A prologue: fill full-K A tile ----
    if (IS_QKV) {
        #pragma unroll
        for (int it = 0; it < 16; it++) {
            int idx = tid + it * 256;       // 0..4095 float4 slots
            int row = idx >> 5;
            int c4  = (idx & 31) * 4;
            int r = m0 + row;
            float4 v = make_float4(0.f, 0.f, 0.f, 0.f);
            if (r < M_TOT) v = *(const float4*)(token_row(r, x, det, inter) + c4);
            float vv[4] = {v.x, v.y, v.z, v.w};
            #pragma unroll
            for (int j = 0; j < 4; j++) {
                __nv_bfloat16 h = __float2bfloat16(vv[j]);
                As_h[row * 136 + c4 + j] = h;
                As_l[row * 136 + c4 + j] = __float2bfloat16(vv[j] - __bfloat162float(h));
            }
        }
    } else {
        #pragma unroll
        for (int it = 0; it < 8; it++) {
            int idx = tid + it * 256;       // 0..2047 uint4 slots per array
            int row = idx >> 4;
            int c8  = (idx & 15) * 8;
            int r = m0 + row;
            uint4 vh = make_uint4(0, 0, 0, 0), vl = make_uint4(0, 0, 0, 0);
            if (r < M_TOT) {
                vh = *(const uint4*)(g_ctx_h + (size_t)r * 128 + c8);
                vl = *(const uint4*)(g_ctx_l + (size_t)r * 128 + c8);
            }
            *(uint4*)(As_h + row * 136 + c8) = vh;
            *(uint4*)(As_l + row * 136 + c8) = vl;
        }
    }

    const int NB = IS_QKV ? 3 : 1;
    for (int nb = 0; nb < NB; nb++) {
        const int n0 = nb * 128;
        float c[2][8][4] = {};
        uint4 pbh[2], pbl[2];
        // prefetch B chunk 0
        #pragma unroll
        for (int it = 0; it < 2; it++) {
            int idx = tid + it * 256;       // 0..511
            int row = idx >> 2, c8 = (idx & 3) * 8;
            pbh[it] = *(const uint4*)(Wh + (size_t)(n0 + row) * 128 + c8);
            pbl[it] = *(const uint4*)(Wl + (size_t)(n0 + row) * 128 + c8);
        }
        #pragma unroll
        for (int kc = 0; kc < 4; kc++) {
            #pragma unroll
            for (int it = 0; it < 2; it++) {
                int idx = tid + it * 256;
                int row = idx >> 2, c8 = (idx & 3) * 8;
                *(uint4*)(Bs_h + row * 40 + c8) = pbh[it];
                *(uint4*)(Bs_l + row * 40 + c8) = pbl[it];
            }
            __syncthreads();
            if (kc < 3) {
                int kk = (kc + 1) * 32;
                #pragma unroll
                for (int it = 0; it < 2; it++) {
                    int idx = tid + it * 256;
                    int row = idx >> 2, c8 = (idx & 3) * 8;
                    pbh[it] = *(const uint4*)(Wh + (size_t)(n0 + row) * 128 + kk + c8);
                    pbl[it] = *(const uint4*)(Wl + (size_t)(n0 + row) * 128 + kk + c8);
                }
            }
            #pragma unroll
            for (int kt = 0; kt < 32; kt += 16) {
                uint32_t ah[2][4], al[2][4];
                const int arow = mbase + (lane & 15);
                const int acol = kc * 32 + kt + ((lane >> 4) << 3);
                ldm_x4(ah[0], As_h + arow * 136 + acol);
                ldm_x4(al[0], As_l + arow * 136 + acol);
                ldm_x4(ah[1], As_h + (arow + 16) * 136 + acol);
                ldm_x4(al[1], As_l + (arow + 16) * 136 + acol);
                #pragma unroll
                for (int np = 0; np < 4; np++) {
                    int mtx  = lane >> 3;
                    int nrow = nbase + (np * 2 + (mtx >> 1)) * 8 + (lane & 7);
                    int kcol = kt + (mtx & 1) * 8;
                    uint32_t bh[4], bl[4];
                    ldm_x4(bh, Bs_h + nrow * 40 + kcol);
                    ldm_x4(bl, Bs_l + nrow * 40 + kcol);
                    #pragma unroll
                    for (int mi = 0; mi < 2; mi++)
                        #pragma unroll
                        for (int j = 0; j < 2; j++) {
                            mma_bf16(c[mi][np * 2 + j], ah[mi], bh[2 * j], bh[2 * j + 1]);
                            mma_bf16(c[mi][np * 2 + j], ah[mi], bl[2 * j], bl[2 * j + 1]);
                            mma_bf16(c[mi][np * 2 + j], al[mi], bh[2 * j], bh[2 * j + 1]);
                        }
                }
            }
            __syncthreads();
        }
        // ---- epilogue for this n-block ----
        const int g = lane >> 2, t = lane & 3;
        #pragma unroll
        for (int ni = 0; ni < 8; ni++) {
            int col = n0 + nbase + ni * 8 + t * 2;
            float2 bb = *(const float2*)(bias + col);
            #pragma unroll
            for (int mi = 0; mi < 2; mi++) {
                #pragma unroll
                for (int rr = 0; rr < 2; rr++) {
                    int r = m0 + mbase + mi * 16 + g + rr * 8;
                    if (r < M_TOT) {
                        float v0 = c[mi][ni][rr * 2 + 0] + bb.x;
                        float v1 = c[mi][ni][rr * 2 + 1] + bb.y;
                        if (IS_QKV) {
                            split_store2(v0, v1, g_qkv_h, g_qkv_l,
                                         (size_t)r * 384 + col);
                        } else {
                            *(float2*)(out_f32 + (size_t)r * 128 + col) =
                                make_float2(v0, v1);
                        }
                    }
                }
            }
        }
    }
}

// ---------------------------------------------------------------------------
// K2: windowed attention (tensor-core). Loads are straight bf16 copies.
// ---------------------------------------------------------------------------
__global__ __launch_bounds__(128)
void win_attn_mma_kernel(const float* __restrict__ mask)
{
    const int h  = blockIdx.x;
    const int w  = blockIdx.y;
    const int b  = blockIdx.z;
    const int hy = w >> 5, wx = w & 31;
    const int tid  = threadIdx.x;
    const int lane = tid & 31;
    const int warp = tid >> 5;

    __shared__ __align__(16) __nv_bfloat16 sqh[64 * 40], sql[64 * 40];
    __shared__ __align__(16) __nv_bfloat16 skh[64 * 40], skl[64 * 40];
    __shared__ __align__(16) __nv_bfloat16 svh[64 * 40], svl[64 * 40];

    // ---- load q,k,v: straight uint4 copies of hi/lo bf16 ----
    #pragma unroll
    for (int it = 0; it < 6; it++) {
        int idx = tid + it * 128;            // 0..767
        int mtx = idx >> 8;                  // 0=q 1=k 2=v
        int rem = idx & 255;
        int tok = rem >> 2;
        int c8  = (rem & 3) * 8;
        int wi = tok >> 3, wj = tok & 7;
        int t = (hy * 8 + wi) * 256 + (wx * 8 + wj);
        size_t base = ((size_t)(b * T_TOT + t)) * 384 + (size_t)mtx * 128 + h * 32 + c8;
        uint4 hv = *(const uint4*)(g_qkv_h + base);
        uint4 lv = *(const uint4*)(g_qkv_l + base);
        __nv_bfloat16* dh = (mtx == 0) ? sqh : (mtx == 1) ? skh : svh;
        __nv_bfloat16* dl = (mtx == 0) ? sql : (mtx == 1) ? skl : svl;
        *(uint4*)(dh + tok * 40 + c8) = hv;
        *(uint4*)(dl + tok * 40 + c8) = lv;
    }
    __syncthreads();

    // ---- S = Q K^T ----
    const int mrow = warp * 16;
    float sc[8][4] = {};
    #pragma unroll
    for (int kt = 0; kt < 32; kt += 16) {
        uint32_t ah[4], al[4];
        const int arow = mrow + (lane & 15);
        const int acol = kt + ((lane >> 4) << 3);
        ldm_x4(ah, sqh + arow * 40 + acol);
        ldm_x4(al, sql + arow * 40 + acol);
        uint32_t bh[4][4], bl[4][4];
        #pragma unroll
        for (int np = 0; np < 4; np++) {
            int mtx  = lane >> 3;
            int nrow = (np * 2 + (mtx >> 1)) * 8 + (lane & 7);
            int kcol = kt + (mtx & 1) * 8;
            ldm_x4(bh[np], skh + nrow * 40 + kcol);
            ldm_x4(bl[np], skl + nrow * 40 + kcol);
        }
        #pragma unroll
        for (int np = 0; np < 4; np++)
            #pragma unroll
            for (int j = 0; j < 2; j++) {
                mma_bf16(sc[np * 2 + j], ah, bh[np][2 * j], bh[np][2 * j + 1]);
                mma_bf16(sc[np * 2 + j], ah, bl[np][2 * j], bl[np][2 * j + 1]);
                mma_bf16(sc[np * 2 + j], al, bh[np][2 * j], bh[np][2 * j + 1]);
            }
    }

    // ---- softmax in accumulator layout ----
    const int g = lane >> 2;
    const int t = lane & 3;
    const int r0 = mrow + g;
    const float* gbr0 = g_bias + h * (L_WIN * L_WIN) + r0 * 64;
    const float* mkr0 = mask + (size_t)w * (L_WIN * L_WIN) + r0 * 64;
    float mx0 = -1e30f, mx1 = -1e30f;
    #pragma unroll
    for (int j = 0; j < 8; j++) {
        int cbase = j * 8 + t * 2;
        float2 b0 = *(const float2*)(gbr0 + cbase);
        float2 m0 = *(const float2*)(mkr0 + cbase);
        float2 b1 = *(const float2*)(gbr0 + 8 * 64 + cbase);
        float2 m1 = *(const float2*)(mkr0 + 8 * 64 + cbase);
        sc[j][0] = sc[j][0] * SCALE_ + b0.x + m0.x;
        sc[j][1] = sc[j][1] * SCALE_ + b0.y + m0.y;
        sc[j][2] = sc[j][2] * SCALE_ + b1.x + m1.x;
        sc[j][3] = sc[j][3] * SCALE_ + b1.y + m1.y;
        mx0 = fmaxf(mx0, fmaxf(sc[j][0], sc[j][1]));
        mx1 = fmaxf(mx1, fmaxf(sc[j][2], sc[j][3]));
    }
    mx0 = fmaxf(mx0, __shfl_xor_sync(0xffffffffu, mx0, 1));
    mx0 = fmaxf(mx0, __shfl_xor_sync(0xffffffffu, mx0, 2));
    mx1 = fmaxf(mx1, __shfl_xor_sync(0xffffffffu, mx1, 1));
    mx1 = fmaxf(mx1, __shfl_xor_sync(0xffffffffu, mx1, 2));
    float sum0 = 0.f, sum1 = 0.f;
    #pragma unroll
    for (int j = 0; j < 8; j++) {
        sc[j][0] = __expf(sc[j][0] - mx0); sum0 += sc[j][0];
        sc[j][1] = __expf(sc[j][1] - mx0); sum0 += sc[j][1];
        sc[j][2] = __expf(sc[j][2] - mx1); sum1 += sc[j][2];
        sc[j][3] = __expf(sc[j][3] - mx1); sum1 += sc[j][3];
    }
    sum0 += __shfl_xor_sync(0xffffffffu, sum0, 1);
    sum0 += __shfl_xor_sync(0xffffffffu, sum0, 2);
    sum1 += __shfl_xor_sync(0xffffffffu, sum1, 1);
    sum1 += __shfl_xor_sync(0xffffffffu, sum1, 2);
    const float inv0 = 1.0f / sum0, inv1 = 1.0f / sum1;
    #pragma unroll
    for (int j = 0; j < 8; j++) {
        sc[j][0] *= inv0; sc[j][1] *= inv0;
        sc[j][2] *= inv1; sc[j][3] *= inv1;
    }

    // ---- repack P -> A-fragments (hi/lo) ----
    uint32_t pah[4][4], pal[4][4];
    #pragma unroll
    for (int kt2 = 0; kt2 < 4; kt2++) {
        #pragma unroll
        for (int half = 0; half < 2; half++) {
            const float* cc = sc[2 * kt2 + half];
            float h0 = __bfloat162float(__float2bfloat16(cc[0]));
            float h1 = __bfloat162float(__float2bfloat16(cc[1]));
            float h2 = __bfloat162float(__float2bfloat16(cc[2]));
            float h3 = __bfloat162float(__float2bfloat16(cc[3]));
            pah[kt2][half * 2 + 0] = pack_bf16x2(h0, h1);
            pah[kt2][half * 2 + 1] = pack_bf16x2(h2, h3);
            pal[kt2][half * 2 + 0] = pack_bf16x2(cc[0] - h0, cc[1] - h1);
            pal[kt2][half * 2 + 1] = pack_bf16x2(cc[2] - h2, cc[3] - h3);
        }
    }

    // ---- O = P V ----
    float oc[4][4] = {};
    #pragma unroll
    for (int kt2 = 0; kt2 < 4; kt2++) {
        int mtx = lane >> 3;
        int vrow = kt2 * 16 + (mtx & 1) * 8 + (lane & 7);
        uint32_t bh[2][4], bl[2][4];
        #pragma unroll
        for (int half = 0; half < 2; half++) {
            int vcol = half * 16 + (mtx >> 1) * 8;
            ldm_x4_t(bh[half], svh + vrow * 40 + vcol);
            ldm_x4_t(bl[half], svl + vrow * 40 + vcol);
        }
        #pragma unroll
        for (int half = 0; half < 2; half++)
            #pragma unroll
            for (int j = 0; j < 2; j++) {
                mma_bf16(oc[half * 2 + j], pah[kt2], bh[half][2 * j], bh[half][2 * j + 1]);
                mma_bf16(oc[half * 2 + j], pah[kt2], bl[half][2 * j], bl[half][2 * j + 1]);
                mma_bf16(oc[half * 2 + j], pal[kt2], bh[half][2 * j], bh[half][2 * j + 1]);
            }
    }

    // ---- store O as bf16 hi/lo ----
    #pragma unroll
    for (int rr = 0; rr < 2; rr++) {
        int l = r0 + rr * 8;
        int wi = l >> 3, wj = l & 7;
        int tk = (hy * 8 + wi) * 256 + (wx * 8 + wj);
        size_t obase = ((size_t)(b * T_TOT + tk)) * 128 + h * 32;
        #pragma unroll
        for (int ni = 0; ni < 4; ni++) {
            float v0 = rr ? oc[ni][2] : oc[ni][0];
            float v1 = rr ? oc[ni][3] : oc[ni][1];
            split_store2(v0, v1, g_ctx_h, g_ctx_l, obase + ni * 8 + t * 2);
        }
    }
}

// ---------------------------------------------------------------------------
// K3: det/inter token MHA. Warp-per-query. hi+lo reconstructed fp32.
// ---------------------------------------------------------------------------
__global__ __launch_bounds__(128)
void tok_attn_kernel()
{
    const int h  = blockIdx.x;
    const int bt = blockIdx.y;
    const int qc = blockIdx.z;
    const int b  = bt >> 1, ty = bt & 1;
    const int tbase = N_IMG + ty * TD_;
    const int tid = threadIdx.x, lane = tid & 31, warp = tid >> 5;

    __shared__ __align__(16) float kt[32][104];
    __shared__ __align__(16) float vs[100][32];
    __shared__ float ps[4][104];

    for (int idx = tid; idx < 100 * 4; idx += 128) {
        int tok = idx >> 2;
        int c8  = (idx & 3) * 8;
        size_t base = ((size_t)(b * T_TOT + tbase + tok)) * 384 + h * 32 + c8;
        float kf[8], vf[8];
        bf8_sum_to_f32(*(const uint4*)(g_qkv_h + base + 128),
                       *(const uint4*)(g_qkv_l + base + 128), kf);
        bf8_sum_to_f32(*(const uint4*)(g_qkv_h + base + 256),
                       *(const uint4*)(g_qkv_l + base + 256), vf);
        #pragma unroll
        for (int j = 0; j < 8; j++) {
            kt[c8 + j][tok] = kf[j];
            vs[tok][c8 + j] = vf[j];
        }
    }
    __syncthreads();

    const int q = qc * 4 + warp;
    float qv[32];
    {
        size_t base = ((size_t)(b * T_TOT + tbase + q)) * 384 + h * 32;
        #pragma unroll
        for (int c8 = 0; c8 < 32; c8 += 8) {
            float qf[8];
            bf8_sum_to_f32(*(const uint4*)(g_qkv_h + base + c8),
                           *(const uint4*)(g_qkv_l + base + c8), qf);
            #pragma unroll
            for (int j = 0; j < 8; j++) qv[c8 + j] = qf[j] * SCALE_;
        }
    }
    float s[4];
    float mx = -1e30f;
    #pragma unroll
    for (int m = 0; m < 4; m++) {
        int j = lane + m * 32;
        float acc = -1e30f;
        if (j < 100) {
            acc = 0.f;
            #pragma unroll
            for (int d = 0; d < 32; d++) acc += qv[d] * kt[d][j];
        }
        s[m] = acc;
        mx = fmaxf(mx, acc);
    }
    #pragma unroll
    for (int o = 16; o > 0; o >>= 1)
        mx = fmaxf(mx, __shfl_xor_sync(0xffffffffu, mx, o));
    float sum = 0.f;
    #pragma unroll
    for (int m = 0; m < 4; m++) {
        int j = lane + m * 32;
        if (j < 100) { s[m] = __expf(s[m] - mx); sum += s[m]; }
        else s[m] = 0.f;
    }
    #pragma unroll
    for (int o = 16; o > 0; o >>= 1)
        sum += __shfl_xor_sync(0xffffffffu, sum, o);
    float inv = 1.0f / sum;
    #pragma unroll
    for (int m = 0; m < 4; m++) {
        int j = lane + m * 32;
        if (j < 100) ps[warp][j] = s[m] * inv;
    }
    __syncwarp();

    float o = 0.f;
    #pragma unroll 10
    for (int j = 0; j < 100; j++)
        o += ps[warp][j] * vs[j][lane];
    size_t off = ((size_t)(b * T_TOT + tbase + q)) * 128 + h * 32 + lane;
    __nv_bfloat16 hbf = __float2bfloat16(o);
    g_ctx_h[off] = hbf;
    g_ctx_l[off] = __float2bfloat16(o - __bfloat162float(hbf));
}

// ---------------------------------------------------------------------------
// kernel_launch
// ---------------------------------------------------------------------------
extern "C" void kernel_launch(void* const* d_in, const int* in_sizes, int n_in,
                              void* d_out, int out_size)
{
    (void)in_sizes; (void)n_in; (void)out_size;
    const float* x        = (const float*)d_in[0];
    const float* det      = (const float*)d_in[1];
    const float* inter    = (const float*)d_in[2];
    const float* mask     = (const float*)d_in[3];
    const float* W_qkv    = (const float*)d_in[4];
    const float* b_qkv    = (const float*)d_in[5];
    const float* W_proj   = (const float*)d_in[6];
    const float* b_proj   = (const float*)d_in[7];
    const float* rel_tab  = (const float*)d_in[8];
    const int*   rel_idx  = (const int*)d_in[9];
    float* out = (float*)d_out;

    const int m_tiles = (M_TOT + 127) / 128;   // 2055
    const int smem_bytes = (128 * 136 * 2 + 128 * 40 * 2) * 2;  // 90112

    cudaFuncSetAttribute(gemm_kernel<true>,
                         cudaFuncAttributeMaxDynamicSharedMemorySize, smem_bytes);
    cudaFuncSetAttribute(gemm_kernel<false>,
                         cudaFuncAttributeMaxDynamicSharedMemorySize, smem_bytes);

    bias_gather_kernel<<<16, 256>>>(rel_tab, rel_idx);
    weight_split_kernel<<<192, 256>>>(W_qkv, W_proj);
    gemm_kernel<true><<<m_tiles, 256, smem_bytes>>>(x, det, inter, b_qkv, nullptr);
    win_attn_mma_kernel<<<dim3(NH_, NWIN, B_SZ), 128>>>(mask);
    tok_attn_kernel<<<dim3(NH_, B_SZ * 2, 25), 128>>>();
    gemm_kernel<false><<<m_tiles, 256, smem_bytes>>>(nullptr, nullptr, nullptr,
                                                     b_proj, out);
}

// round 13
// speedup vs baseline: 1.1706x; 1.1706x over previous
#include <cuda_runtime.h>
#include <cuda_bf16.h>
#include <cuda_fp16.h>
#include <cstdint>
#include <cstddef>

// ---------------------------------------------------------------------------
// Problem constants
// ---------------------------------------------------------------------------
#define B_SZ   4
#define NH_    4
#define HD_    32
#define C_DIM  128
#define WS_    8
#define L_WIN  64
#define NWIN   1024
#define N_IMG  65536
#define TD_    100
#define T_TOT  65736
#define M_TOT  (B_SZ * T_TOT)   // 262944
#define SCALE_ 0.17677669529663687f

// Scratch (device globals)
__device__ float g_qkv[(size_t)M_TOT * 384];   // [row][3*C]
__device__ float g_ctx[(size_t)M_TOT * 128];   // attention outputs
__device__ __nv_bfloat16 g_wq_h[384 * 128], g_wq_l[384 * 128];
__device__ __nv_bfloat16 g_wp_h[128 * 128], g_wp_l[128 * 128];
__device__ float g_bias[NH_ * L_WIN * L_WIN];

// ---------------------------------------------------------------------------
__device__ __forceinline__ const float* token_row(int r,
                                                  const float* __restrict__ x,
                                                  const float* __restrict__ det,
                                                  const float* __restrict__ inter)
{
    int b = r / T_TOT;
    int t = r - b * T_TOT;
    if (t < N_IMG)  return x     + ((size_t)b * N_IMG + t) * C_DIM;
    t -= N_IMG;
    if (t < TD_)    return det   + ((size_t)b * TD_   + t) * C_DIM;
    return inter + ((size_t)b * TD_ + (t - TD_)) * C_DIM;
}

// ---------------------------------------------------------------------------
// mma helpers (m16n8k16, fp32 accumulate)
// ---------------------------------------------------------------------------
__device__ __forceinline__ void mma_bf16(float c[4], const uint32_t a[4],
                                         uint32_t b0, uint32_t b1)
{
    asm volatile(
        "mma.sync.aligned.m16n8k16.row.col.f32.bf16.bf16.f32 "
        "{%0,%1,%2,%3}, {%4,%5,%6,%7}, {%8,%9}, {%0,%1,%2,%3};\n"
        : "+f"(c[0]), "+f"(c[1]), "+f"(c[2]), "+f"(c[3])
        : "r"(a[0]), "r"(a[1]), "r"(a[2]), "r"(a[3]), "r"(b0), "r"(b1));
}

__device__ __forceinline__ void mma_f16(float c[4], const uint32_t a[4],
                                        uint32_t b0, uint32_t b1)
{
    asm volatile(
        "mma.sync.aligned.m16n8k16.row.col.f32.f16.f16.f32 "
        "{%0,%1,%2,%3}, {%4,%5,%6,%7}, {%8,%9}, {%0,%1,%2,%3};\n"
        : "+f"(c[0]), "+f"(c[1]), "+f"(c[2]), "+f"(c[3])
        : "r"(a[0]), "r"(a[1]), "r"(a[2]), "r"(a[3]), "r"(b0), "r"(b1));
}

__device__ __forceinline__ void ldm_x4(uint32_t r[4], const void* p)
{
    uint32_t sa = (uint32_t)__cvta_generic_to_shared(p);
    asm volatile("ldmatrix.sync.aligned.m8n8.x4.shared.b16 {%0,%1,%2,%3}, [%4];"
                 : "=r"(r[0]), "=r"(r[1]), "=r"(r[2]), "=r"(r[3]) : "r"(sa));
}

__device__ __forceinline__ void ldm_x4_t(uint32_t r[4], const void* p)
{
    uint32_t sa = (uint32_t)__cvta_generic_to_shared(p);
    asm volatile("ldmatrix.sync.aligned.m8n8.x4.trans.shared.b16 {%0,%1,%2,%3}, [%4];"
                 : "=r"(r[0]), "=r"(r[1]), "=r"(r[2]), "=r"(r[3]) : "r"(sa));
}

__device__ __forceinline__ uint32_t pack_bf16x2(float e0, float e1)
{
    uint32_t r;
    asm("cvt.rn.bf16x2.f32 %0, %1, %2;" : "=r"(r) : "f"(e1), "f"(e0));
    return r;
}

// ---------------------------------------------------------------------------
// K0a: pregather rel-pos bias; K0b: split weights to bf16 hi/lo
// ---------------------------------------------------------------------------
__global__ void bias_gather_kernel(const float* __restrict__ rel_table,
                                   const int*   __restrict__ rel_index)
{
    int idx = blockIdx.x * 256 + threadIdx.x;
    if (idx < L_WIN * L_WIN) {
        int ri = rel_index[idx];
        #pragma unroll
        for (int h = 0; h < NH_; h++)
            g_bias[h * (L_WIN * L_WIN) + idx] = rel_table[ri * NH_ + h];
    }
}

__global__ void weight_split_kernel(const float* __restrict__ Wq,
                                    const float* __restrict__ Wp)
{
    int i = blockIdx.x * 256 + threadIdx.x;
    if (i < 384 * 128) {
        float v = Wq[i];
        __nv_bfloat16 h = __float2bfloat16(v);
        g_wq_h[i] = h;
        g_wq_l[i] = __float2bfloat16(v - __bfloat162float(h));
    }
    if (i < 128 * 128) {
        float v = Wp[i];
        __nv_bfloat16 h = __float2bfloat16(v);
        g_wp_h[i] = h;
        g_wp_l[i] = __float2bfloat16(v - __bfloat162float(h));
    }
}

// ---------------------------------------------------------------------------
// Tensor-core GEMM, bf16 hi/lo split (3 products).  R7 structure;
// B path reads pre-split bf16 weights (straight uint4 copies).
// ---------------------------------------------------------------------------
template<bool IS_QKV>
__global__ __launch_bounds__(256, 2)
void mma_gemm_kernel(const float* __restrict__ x, const float* __restrict__ det,
                     const float* __restrict__ inter,
                     const float* __restrict__ bias, float* __restrict__ out_param)
{
    __shared__ __align__(16) __nv_bfloat16 Ah[128][40];
    __shared__ __align__(16) __nv_bfloat16 Al[128][40];
    __shared__ __align__(16) __nv_bfloat16 Bh[128][40];
    __shared__ __align__(16) __nv_bfloat16 Bl[128][40];

    const __nv_bfloat16* Wh = IS_QKV ? g_wq_h : g_wp_h;
    const __nv_bfloat16* Wl = IS_QKV ? g_wq_l : g_wp_l;
    float* outp = IS_QKV ? g_qkv : out_param;
    const int ldo = IS_QKV ? 384 : 128;

    const int m0   = blockIdx.y * 128;
    const int n0   = blockIdx.x * 128;
    const int tid  = threadIdx.x;
    const int lane = tid & 31;
    const int warp = tid >> 5;
    const int mbase = (warp >> 1) * 32;
    const int nbase = (warp & 1) * 64;

    float c[2][8][4] = {};
    float4 pa[4];
    uint4  pbh[2], pbl[2];

    // prologue: load chunk 0
    #pragma unroll
    for (int it = 0; it < 4; it++) {
        int idx = tid + it * 256;
        int row = idx >> 3;
        int c4  = (idx & 7) * 4;
        int r = m0 + row;
        pa[it] = make_float4(0.f, 0.f, 0.f, 0.f);
        if (r < M_TOT) {
            if (IS_QKV) pa[it] = *(const float4*)(token_row(r, x, det, inter) + c4);
            else        pa[it] = *(const float4*)(g_ctx + (size_t)r * 128 + c4);
        }
    }
    #pragma unroll
    for (int it = 0; it < 2; it++) {
        int idx = tid + it * 256;          // 0..511
        int row = idx >> 2, c8 = (idx & 3) * 8;
        pbh[it] = *(const uint4*)(Wh + (size_t)(n0 + row) * 128 + c8);
        pbl[it] = *(const uint4*)(Wl + (size_t)(n0 + row) * 128 + c8);
    }

    #pragma unroll
    for (int kc = 0; kc < 4; kc++) {
        // ---- store staged regs -> smem ----
        #pragma unroll
        for (int it = 0; it < 4; it++) {
            int idx = tid + it * 256;
            int row = idx >> 3;
            int c4  = (idx & 7) * 4;
            float va[4] = {pa[it].x, pa[it].y, pa[it].z, pa[it].w};
            #pragma unroll
            for (int j = 0; j < 4; j++) {
                __nv_bfloat16 h = __float2bfloat16(va[j]);
                Ah[row][c4 + j] = h;
                Al[row][c4 + j] = __float2bfloat16(va[j] - __bfloat162float(h));
            }
        }
        #pragma unroll
        for (int it = 0; it < 2; it++) {
            int idx = tid + it * 256;
            int row = idx >> 2, c8 = (idx & 3) * 8;
            *(uint4*)&Bh[row][c8] = pbh[it];
            *(uint4*)&Bl[row][c8] = pbl[it];
        }
        __syncthreads();

        // ---- prefetch next chunk ----
        if (kc < 3) {
            int kk = (kc + 1) * 32;
            #pragma unroll
            for (int it = 0; it < 4; it++) {
                int idx = tid + it * 256;
                int row = idx >> 3;
                int c4  = (idx & 7) * 4;
                int r = m0 + row;
                pa[it] = make_float4(0.f, 0.f, 0.f, 0.f);
                if (r < M_TOT) {
                    if (IS_QKV) pa[it] = *(const float4*)(token_row(r, x, det, inter) + kk + c4);
                    else        pa[it] = *(const float4*)(g_ctx + (size_t)r * 128 + kk + c4);
                }
            }
            #pragma unroll
            for (int it = 0; it < 2; it++) {
                int idx = tid + it * 256;
                int row = idx >> 2, c8 = (idx & 3) * 8;
                pbh[it] = *(const uint4*)(Wh + (size_t)(n0 + row) * 128 + kk + c8);
                pbl[it] = *(const uint4*)(Wl + (size_t)(n0 + row) * 128 + kk + c8);
            }
        }

        // ---- compute on current smem chunk ----
        #pragma unroll
        for (int kt = 0; kt < 32; kt += 16) {
            uint32_t ah[2][4], al[2][4];
            const int arow_in = lane & 15;
            const int acol = kt + ((lane >> 4) << 3);
            #pragma unroll
            for (int mi = 0; mi < 2; mi++) {
                ldm_x4(ah[mi], &Ah[mbase + mi * 16 + arow_in][acol]);
                ldm_x4(al[mi], &Al[mbase + mi * 16 + arow_in][acol]);
            }
            #pragma unroll
            for (int np = 0; np < 4; np++) {
                int mtx  = lane >> 3;
                int nrow = nbase + (np * 2 + (mtx >> 1)) * 8 + (lane & 7);
                int kcol = kt + (mtx & 1) * 8;
                uint32_t bh[4], bl[4];
                ldm_x4(bh, &Bh[nrow][kcol]);
                ldm_x4(bl, &Bl[nrow][kcol]);
                #pragma unroll
                for (int mi = 0; mi < 2; mi++)
                    #pragma unroll
                    for (int j = 0; j < 2; j++) {
                        mma_bf16(c[mi][np * 2 + j], ah[mi], bh[2 * j], bh[2 * j + 1]);
                        mma_bf16(c[mi][np * 2 + j], ah[mi], bl[2 * j], bl[2 * j + 1]);
                        mma_bf16(c[mi][np * 2 + j], al[mi], bh[2 * j], bh[2 * j + 1]);
                    }
            }
        }
        __syncthreads();
    }

    const int g = lane >> 2;
    const int t = lane & 3;
    #pragma unroll
    for (int ni = 0; ni < 8; ni++) {
        int col = n0 + nbase + ni * 8 + t * 2;
        float2 bb = *(const float2*)(bias + col);
        #pragma unroll
        for (int mi = 0; mi < 2; mi++) {
            int r0 = m0 + mbase + mi * 16 + g;
            if (r0 < M_TOT) {
                float2 v = make_float2(c[mi][ni][0] + bb.x, c[mi][ni][1] + bb.y);
                *(float2*)(outp + (size_t)r0 * ldo + col) = v;
            }
            int r1 = r0 + 8;
            if (r1 < M_TOT) {
                float2 v = make_float2(c[mi][ni][2] + bb.x, c[mi][ni][3] + bb.y);
                *(float2*)(outp + (size_t)r1 * ldo + col) = v;
            }
        }
    }
}

// ---------------------------------------------------------------------------
// K2: windowed attention.  S phase: single-precision fp16 (1 mma/group).
// PV phase: bf16 hi/lo 3-term (accuracy-critical).
// ---------------------------------------------------------------------------
__global__ __launch_bounds__(128)
void win_attn_mma_kernel(const float* __restrict__ mask)
{
    const int h  = blockIdx.x;
    const int w  = blockIdx.y;
    const int b  = blockIdx.z;
    const int hy = w >> 5, wx = w & 31;
    const int tid  = threadIdx.x;
    const int lane = tid & 31;
    const int warp = tid >> 5;

    __shared__ __align__(16) __half      qs[64][40];
    __shared__ __align__(16) __half      ks[64][40];
    __shared__ __align__(16) __nv_bfloat16 vh[64][40], vl[64][40];

    // ---- load q,k (fp16 single) and v (bf16 hi/lo) ----
    #pragma unroll
    for (int it = 0; it < 12; it++) {
        int idx = tid + it * 128;        // 0..1535 float4 slots
        int mtx = idx / 512;             // 0=q 1=k 2=v
        int rem = idx - mtx * 512;
        int tok = rem >> 3;
        int c4  = (rem & 7) * 4;
        int wi = tok >> 3, wj = tok & 7;
        int t = (hy * 8 + wi) * 256 + (wx * 8 + wj);
        size_t base = ((size_t)(b * T_TOT + t)) * 384 + (size_t)mtx * 128 + h * 32;
        float4 v4 = *(const float4*)(g_qkv + base + c4);
        if (mtx < 2) {
            __half2 p0 = __floats2half2_rn(v4.x, v4.y);
            __half2 p1 = __floats2half2_rn(v4.z, v4.w);
            __half* dst = (mtx == 0) ? &qs[0][0] : &ks[0][0];
            *(__half2*)(dst + tok * 40 + c4)     = p0;
            *(__half2*)(dst + tok * 40 + c4 + 2) = p1;
        } else {
            float vv[4] = {v4.x, v4.y, v4.z, v4.w};
            #pragma unroll
            for (int j = 0; j < 4; j++) {
                __nv_bfloat16 hi = __float2bfloat16(vv[j]);
                vh[tok][c4 + j] = hi;
                vl[tok][c4 + j] = __float2bfloat16(vv[j] - __bfloat162float(hi));
            }
        }
    }
    __syncthreads();

    // ---- S = Q K^T (fp16, single product) ----
    const int mrow = warp * 16;
    float sc[8][4] = {};
    #pragma unroll
    for (int kt = 0; kt < 32; kt += 16) {
        uint32_t aq[4];
        const int arow = mrow + (lane & 15);
        const int acol = kt + ((lane >> 4) << 3);
        ldm_x4(aq, &qs[arow][acol]);
        #pragma unroll
        for (int np = 0; np < 4; np++) {
            int mtx  = lane >> 3;
            int nrow = (np * 2 + (mtx >> 1)) * 8 + (lane & 7);
            int kcol = kt + (mtx & 1) * 8;
            uint32_t bq[4];
            ldm_x4(bq, &ks[nrow][kcol]);
            #pragma unroll
            for (int j = 0; j < 2; j++)
                mma_f16(sc[np * 2 + j], aq, bq[2 * j], bq[2 * j + 1]);
        }
    }

    // ---- softmax in accumulator layout (bias+mask direct from global) ----
    const int g = lane >> 2;
    const int t = lane & 3;
    const int r0 = mrow + g;
    const float* gbr0 = g_bias + h * (L_WIN * L_WIN) + r0 * 64;
    const float* mkr0 = mask + (size_t)w * (L_WIN * L_WIN) + r0 * 64;
    float mx0 = -1e30f, mx1 = -1e30f;
    #pragma unroll
    for (int j = 0; j < 8; j++) {
        int cbase = j * 8 + t * 2;
        float2 b0 = *(const float2*)(gbr0 + cbase);
        float2 m0 = *(const float2*)(mkr0 + cbase);
        float2 b1 = *(const float2*)(gbr0 + 8 * 64 + cbase);
        float2 m1 = *(const float2*)(mkr0 + 8 * 64 + cbase);
        sc[j][0] = sc[j][0] * SCALE_ + b0.x + m0.x;
        sc[j][1] = sc[j][1] * SCALE_ + b0.y + m0.y;
        sc[j][2] = sc[j][2] * SCALE_ + b1.x + m1.x;
        sc[j][3] = sc[j][3] * SCALE_ + b1.y + m1.y;
        mx0 = fmaxf(mx0, fmaxf(sc[j][0], sc[j][1]));
        mx1 = fmaxf(mx1, fmaxf(sc[j][2], sc[j][3]));
    }
    mx0 = fmaxf(mx0, __shfl_xor_sync(0xffffffffu, mx0, 1));
    mx0 = fmaxf(mx0, __shfl_xor_sync(0xffffffffu, mx0, 2));
    mx1 = fmaxf(mx1, __shfl_xor_sync(0xffffffffu, mx1, 1));
    mx1 = fmaxf(mx1, __shfl_xor_sync(0xffffffffu, mx1, 2));
    float sum0 = 0.f, sum1 = 0.f;
    #pragma unroll
    for (int j = 0; j < 8; j++) {
        sc[j][0] = __expf(sc[j][0] - mx0); sum0 += sc[j][0];
        sc[j][1] = __expf(sc[j][1] - mx0); sum0 += sc[j][1];
        sc[j][2] = __expf(sc[j][2] - mx1); sum1 += sc[j][2];
        sc[j][3] = __expf(sc[j][3] - mx1); sum1 += sc[j][3];
    }
    sum0 += __shfl_xor_sync(0xffffffffu, sum0, 1);
    sum0 += __shfl_xor_sync(0xffffffffu, sum0, 2);
    sum1 += __shfl_xor_sync(0xffffffffu, sum1, 1);
    sum1 += __shfl_xor_sync(0xffffffffu, sum1, 2);
    const float inv0 = 1.0f / sum0, inv1 = 1.0f / sum1;
    #pragma unroll
    for (int j = 0; j < 8; j++) {
        sc[j][0] *= inv0; sc[j][1] *= inv0;
        sc[j][2] *= inv1; sc[j][3] *= inv1;
    }

    // ---- repack P -> A-fragments (bf16 hi/lo) ----
    uint32_t pah[4][4], pal[4][4];
    #pragma unroll
    for (int kt2 = 0; kt2 < 4; kt2++) {
        #pragma unroll
        for (int half = 0; half < 2; half++) {
            const float* cc = sc[2 * kt2 + half];
            float h0 = __bfloat162float(__float2bfloat16(cc[0]));
            float h1 = __bfloat162float(__float2bfloat16(cc[1]));
            float h2 = __bfloat162float(__float2bfloat16(cc[2]));
            float h3 = __bfloat162float(__float2bfloat16(cc[3]));
            pah[kt2][half * 2 + 0] = pack_bf16x2(h0, h1);
            pah[kt2][half * 2 + 1] = pack_bf16x2(h2, h3);
            pal[kt2][half * 2 + 0] = pack_bf16x2(cc[0] - h0, cc[1] - h1);
            pal[kt2][half * 2 + 1] = pack_bf16x2(cc[2] - h2, cc[3] - h3);
        }
    }

    // ---- O = P V (bf16 hi/lo, 3-term) ----
    float oc[4][4] = {};
    #pragma unroll
    for (int kt2 = 0; kt2 < 4; kt2++) {
        int mtx = lane >> 3;
        int vrow = kt2 * 16 + (mtx & 1) * 8 + (lane & 7);
        uint32_t bh[2][4], bl[2][4];
        #pragma unroll
        for (int half = 0; half < 2; half++) {
            int vcol = half * 16 + (mtx >> 1) * 8;
            ldm_x4_t(bh[half], &vh[vrow][vcol]);
            ldm_x4_t(bl[half], &vl[vrow][vcol]);
        }
        #pragma unroll
        for (int half = 0; half < 2; half++)
            #pragma unroll
            for (int j = 0; j < 2; j++) {
                mma_bf16(oc[half * 2 + j], pah[kt2], bh[half][2 * j], bh[half][2 * j + 1]);
                mma_bf16(oc[half * 2 + j], pah[kt2], bl[half][2 * j], bl[half][2 * j + 1]);
                mma_bf16(oc[half * 2 + j], pal[kt2], bh[half][2 * j], bh[half][2 * j + 1]);
            }
    }

    // ---- store O ----
    #pragma unroll
    for (int rr = 0; rr < 2; rr++) {
        int l = r0 + rr * 8;
        int wi = l >> 3, wj = l & 7;
        int tk = (hy * 8 + wi) * 256 + (wx * 8 + wj);
        float* op = g_ctx + ((size_t)(b * T_TOT + tk)) * 128 + h * 32;
        #pragma unroll
        for (int ni = 0; ni < 4; ni++) {
            float2 v = rr ? make_float2(oc[ni][2], oc[ni][3])
                          : make_float2(oc[ni][0], oc[ni][1]);
            *(float2*)(op + ni * 8 + t * 2) = v;
        }
    }
}

// ---------------------------------------------------------------------------
// K3: det/inter token MHA (R7 version).
// ---------------------------------------------------------------------------
__global__ __launch_bounds__(128)
void tok_attn_kernel()
{
    const int h  = blockIdx.x;
    const int bt = blockIdx.y;
    const int qc = blockIdx.z;
    const int b  = bt >> 1, ty = bt & 1;
    const int tbase = N_IMG + ty * TD_;
    const int tid = threadIdx.x, lane = tid & 31, warp = tid >> 5;

    __shared__ __align__(16) float kt[32][104];
    __shared__ __align__(16) float vs[100][32];
    __shared__ float ps[4][104];

    for (int idx = tid; idx < 100 * 8; idx += 128) {
        int tok = idx >> 3;
        int c4  = (idx & 7) * 4;
        size_t base = ((size_t)(b * T_TOT + tbase + tok)) * 384 + h * 32;
        float4 kv = *(const float4*)(g_qkv + base + 128 + c4);
        kt[c4 + 0][tok] = kv.x; kt[c4 + 1][tok] = kv.y;
        kt[c4 + 2][tok] = kv.z; kt[c4 + 3][tok] = kv.w;
        *(float4*)&vs[tok][c4] = *(const float4*)(g_qkv + base + 256 + c4);
    }
    __syncthreads();

    const int q = qc * 4 + warp;
    float qv[32];
    {
        const float* qp = g_qkv + ((size_t)(b * T_TOT + tbase + q)) * 384 + h * 32;
        #pragma unroll
        for (int d4 = 0; d4 < 8; d4++) {
            float4 v = *(const float4*)(qp + d4 * 4);
            qv[d4*4+0] = v.x * SCALE_; qv[d4*4+1] = v.y * SCALE_;
            qv[d4*4+2] = v.z * SCALE_; qv[d4*4+3] = v.w * SCALE_;
        }
    }
    float s[4];
    float mx = -1e30f;
    #pragma unroll
    for (int m = 0; m < 4; m++) {
        int j = lane + m * 32;
        float acc = -1e30f;
        if (j < 100) {
            acc = 0.f;
            #pragma unroll
            for (int d = 0; d < 32; d++) acc += qv[d] * kt[d][j];
        }
        s[m] = acc;
        mx = fmaxf(mx, acc);
    }
    #pragma unroll
    for (int o = 16; o > 0; o >>= 1)
        mx = fmaxf(mx, __shfl_xor_sync(0xffffffffu, mx, o));
    float sum = 0.f;
    #pragma unroll
    for (int m = 0; m < 4; m++) {
        int j = lane + m * 32;
        if (j < 100) { s[m] = __expf(s[m] - mx); sum += s[m]; }
        else s[m] = 0.f;
    }
    #pragma unroll
    for (int o = 16; o > 0; o >>= 1)
        sum += __shfl_xor_sync(0xffffffffu, sum, o);
    float inv = 1.0f / sum;
    #pragma unroll
    for (int m = 0; m < 4; m++) {
        int j = lane + m * 32;
        if (j < 100) ps[warp][j] = s[m] * inv;
    }
    __syncwarp();

    float o = 0.f;
    #pragma unroll 10
    for (int j = 0; j < 100; j++)
        o += ps[warp][j] * vs[j][lane];
    g_ctx[((size_t)(b * T_TOT + tbase + q)) * 128 + h * 32 + lane] = o;
}

// ---------------------------------------------------------------------------
// kernel_launch
// ---------------------------------------------------------------------------
extern "C" void kernel_launch(void* const* d_in, const int* in_sizes, int n_in,
                              void* d_out, int out_size)
{
    (void)in_sizes; (void)n_in; (void)out_size;
    const float* x        = (const float*)d_in[0];
    const float* det      = (const float*)d_in[1];
    const float* inter    = (const float*)d_in[2];
    const float* mask     = (const float*)d_in[3];
    const float* W_qkv    = (const float*)d_in[4];
    const float* b_qkv    = (const float*)d_in[5];
    const float* W_proj   = (const float*)d_in[6];
    const float* b_proj   = (const float*)d_in[7];
    const float* rel_tab  = (const float*)d_in[8];
    const int*   rel_idx  = (const int*)d_in[9];
    float* out = (float*)d_out;

    const int m_tiles = (M_TOT + 127) / 128;   // 2055

    bias_gather_kernel<<<16, 256>>>(rel_tab, rel_idx);
    weight_split_kernel<<<192, 256>>>(W_qkv, W_proj);
    mma_gemm_kernel<true><<<dim3(3, m_tiles), 256>>>(x, det, inter, b_qkv, nullptr);
    win_attn_mma_kernel<<<dim3(NH_, NWIN, B_SZ), 128>>>(mask);
    tok_attn_kernel<<<dim3(NH_, B_SZ * 2, 25), 128>>>();
    mma_gemm_kernel<false><<<dim3(1, m_tiles), 256>>>(nullptr, nullptr, nullptr,
                                                      b_proj, out);
}